// round 8
// baseline (speedup 1.0000x reference)
#include <cuda_runtime.h>
#include <cuda_fp16.h>
#include <math.h>

// ---------------------------------------------------------------------------
// SHINE heterogeneous GCN — CSR counting sort, fp16-staged gather SpMM with
// half-warp edge pairing (uint4 gathers, 4-edge MLP), register-tiled GEMM,
// fused doc-agg + L2 norm.
// ---------------------------------------------------------------------------
#define N_DOC    10000
#define N_WORD   20000
#define N_ENT    10000
#define N_POS    60
#define DIM      128
#define D_POS_IN 60
#define D_WEMB   300
#define EPSN     1e-9f

#define E11 320000
#define E22 160000
#define E33 3600
#define E01 300000
#define E02 100000
#define E03 150000
#define TOT_E (E11 + E22 + E33 + E01 + E02 + E03)   // 1,033,600

// Counter-segment bases (order: a11, a22, a33, a01, a02, a03)
#define C11 0
#define C22 (C11 + N_WORD)   // 20000
#define C33 (C22 + N_ENT)    // 30000
#define C01 (C33 + N_POS)    // 30060
#define C02 (C01 + N_DOC)    // 40060
#define C03 (C02 + N_DOC)    // 50060
#define CTOT (C03 + N_DOC)   // 60060

// Edge-buffer segment bases
#define B11 0
#define B22 (B11 + E11)
#define B33 (B22 + E22)
#define B01 (B33 + E33)
#define B02 (B01 + E01)
#define B03 (B02 + E02)

// ---------------------------------------------------------------------------
// static scratch
__device__ __align__(16) float2 g_sorted[TOT_E];   // row-sorted (col_bits, val)
__device__ __align__(16) int    g_cnt[CTOT];
__device__ __align__(16) int    g_off[CTOT];       // after bucket: inclusive prefix

// fp16-staged gather sources (rows 256B-aligned => uint4-clean)
__device__ __align__(16) __half g_f1h  [N_WORD * DIM];
__device__ __align__(16) __half g_f2h  [N_ENT  * DIM];
__device__ __align__(16) __half g_wembh[N_ENT  * D_WEMB];
__device__ __align__(16) __half g_g1   [N_WORD * DIM];
__device__ __align__(16) __half g_g2   [N_ENT  * DIM];
__device__ __align__(16) __half g_g3   [N_POS  * DIM];
__device__ __align__(16) __half g_g3b  [N_POS  * DIM];
__device__ __align__(16) __half g_tmpB [N_WORD * DIM];
__device__ __align__(16) __half g_tmp2b[N_ENT  * DIM];
__device__ __align__(16) __half g_tmp3b[N_POS  * DIM];

// fp32 GEMM inputs (read linearly, not gathered)
__device__ __align__(16) float g_tmpA[N_WORD * DIM];
__device__ __align__(16) float g_tmp2[N_ENT  * DIM];
__device__ __align__(16) float g_tmp3[N_POS  * DIM];

struct EdgePtrs {
    const int *r11, *c11; const float *v11;
    const int *r22, *c22; const float *v22;
    const int *r33, *c33; const float *v33;
    const int *r01, *c01; const float *v01;
    const int *r02, *c02; const float *v02;
    const int *r03, *c03; const float *v03;
};

// ---------------------------------------------------------------------------
__device__ __forceinline__ float4 relu4(float4 t) {
    t.x = fmaxf(t.x, 0.f); t.y = fmaxf(t.y, 0.f);
    t.z = fmaxf(t.z, 0.f); t.w = fmaxf(t.w, 0.f);
    return t;
}
__device__ __forceinline__ void fma4(float4& a, float s, float4 t) {
    a.x = fmaf(s, t.x, a.x); a.y = fmaf(s, t.y, a.y);
    a.z = fmaf(s, t.z, a.z); a.w = fmaf(s, t.w, a.w);
}
__device__ __forceinline__ void add4(float4& a, float4 t) {
    a.x += t.x; a.y += t.y; a.z += t.z; a.w += t.w;
}
__device__ __forceinline__ float dot4(float4 a) {
    return a.x * a.x + a.y * a.y + a.z * a.z + a.w * a.w;
}
// 8B load of 4 halves -> float4
__device__ __forceinline__ float4 ldg_h4(const __half* base, int unit) {
    uint2 u = __ldg((const uint2*)base + unit);
    __half2 a = *reinterpret_cast<__half2*>(&u.x);
    __half2 b = *reinterpret_cast<__half2*>(&u.y);
    float2 fa = __half22float2(a), fb = __half22float2(b);
    return make_float4(fa.x, fa.y, fb.x, fb.y);
}
__device__ __forceinline__ void st_h4(__half* base, int unit, float4 v) {
    __half2 a = __floats2half2_rn(v.x, v.y);
    __half2 b = __floats2half2_rn(v.z, v.w);
    uint2 u;
    u.x = *reinterpret_cast<unsigned*>(&a);
    u.y = *reinterpret_cast<unsigned*>(&b);
    ((uint2*)base)[unit] = u;
}
// 16B -> 8 floats
__device__ __forceinline__ void h8_to_f(uint4 u, float4& lo, float4& hi) {
    __half2 a = *reinterpret_cast<__half2*>(&u.x);
    __half2 b = *reinterpret_cast<__half2*>(&u.y);
    __half2 c = *reinterpret_cast<__half2*>(&u.z);
    __half2 d = *reinterpret_cast<__half2*>(&u.w);
    float2 fa = __half22float2(a), fb = __half22float2(b);
    float2 fc = __half22float2(c), fd = __half22float2(d);
    lo = make_float4(fa.x, fa.y, fb.x, fb.y);
    hi = make_float4(fc.x, fc.y, fd.x, fd.y);
}
__device__ __forceinline__ float4 shfl_xor4(float4 v, int m) {
    return make_float4(__shfl_xor_sync(0xffffffffu, v.x, m),
                       __shfl_xor_sync(0xffffffffu, v.y, m),
                       __shfl_xor_sync(0xffffffffu, v.z, m),
                       __shfl_xor_sync(0xffffffffu, v.w, m));
}

// ---------------------------------------------------------------------------
// Half-warp-paired SpMM row accumulator over fp16 rows (256B = 16 uint4).
// Lanes 0-15 handle even edges, 16-31 odd edges; one uint4 gather per lane
// covers 8 halves. Two edge-pairs in flight (MLP=4 on the gather path).
// Returns this lane's final output unit value; unit index = 2*(lane&15)+half.
template <bool RELU>
__device__ __forceinline__ float4 spmm_row_sel(int gi, const __half* __restrict__ x, int lane) {
    const int hl   = lane & 15;
    const int half = lane >> 4;
    int s = (gi == 0) ? 0 : __ldg(g_off + gi - 1);
    int e = __ldg(g_off + gi);

    float4 a0 = make_float4(0.f,0.f,0.f,0.f), a1 = a0, b0 = a0, b1 = a0;
    int k = s;
    for (; k + 3 < e; k += 4) {
        float2 cA = __ldg(&g_sorted[k + half]);
        float2 cB = __ldg(&g_sorted[k + 2 + half]);
        uint4 uA = __ldg((const uint4*)(x + (size_t)__float_as_int(cA.x) * DIM) + hl);
        uint4 uB = __ldg((const uint4*)(x + (size_t)__float_as_int(cB.x) * DIM) + hl);
        float4 fA0, fA1, fB0, fB1;
        h8_to_f(uA, fA0, fA1);
        h8_to_f(uB, fB0, fB1);
        if (RELU) { fA0 = relu4(fA0); fA1 = relu4(fA1); fB0 = relu4(fB0); fB1 = relu4(fB1); }
        fma4(a0, cA.y, fA0); fma4(a1, cA.y, fA1);
        fma4(b0, cB.y, fB0); fma4(b1, cB.y, fB1);
    }
    for (; k + 1 < e; k += 2) {
        float2 cv = __ldg(&g_sorted[k + half]);
        uint4 u = __ldg((const uint4*)(x + (size_t)__float_as_int(cv.x) * DIM) + hl);
        float4 f0, f1;
        h8_to_f(u, f0, f1);
        if (RELU) { f0 = relu4(f0); f1 = relu4(f1); }
        fma4(a0, cv.y, f0); fma4(a1, cv.y, f1);
    }
    if (k < e && half == 0) {   // odd leftover edge: lanes 0-15 only
        float2 cv = __ldg(&g_sorted[k]);
        uint4 u = __ldg((const uint4*)(x + (size_t)__float_as_int(cv.x) * DIM) + hl);
        float4 f0, f1;
        h8_to_f(u, f0, f1);
        if (RELU) { f0 = relu4(f0); f1 = relu4(f1); }
        fma4(a0, cv.y, f0); fma4(a1, cv.y, f1);
    }
    add4(a0, b0); add4(a1, b1);
    // cross-half combine: both halves end with identical totals
    add4(a0, shfl_xor4(a0, 16));
    add4(a1, shfl_xor4(a1, 16));
    return half ? a1 : a0;
}

// ---------------------------------------------------------------------------
// register-tiled GEMM: one warp computes 4 rows x 128 cols, output fp32 or fp16
__device__ __forceinline__ void gemm_store(float* p, int lane, float4 v) {
    ((float4*)p)[lane] = v;
}
__device__ __forceinline__ void gemm_store(__half* p, int lane, float4 v) {
    st_h4(p, lane, v);
}

template <bool RELU_A, typename OutT>
__device__ __forceinline__ void gemm4_rows(const float* __restrict__ A,
                                           const float* __restrict__ W,
                                           const float* __restrict__ bias,
                                           OutT* __restrict__ C,
                                           int r0, int K, int lane)
{
    float4 a0 = make_float4(0,0,0,0), a1 = a0, a2 = a0, a3 = a0;
    if (4 * lane < K) {
        a0 = *(const float4*)(A + (size_t)(r0 + 0) * K + 4 * lane);
        a1 = *(const float4*)(A + (size_t)(r0 + 1) * K + 4 * lane);
        a2 = *(const float4*)(A + (size_t)(r0 + 2) * K + 4 * lane);
        a3 = *(const float4*)(A + (size_t)(r0 + 3) * K + 4 * lane);
        if (RELU_A) { a0 = relu4(a0); a1 = relu4(a1); a2 = relu4(a2); a3 = relu4(a3); }
    }
    float4 bf = __ldg((const float4*)bias + lane);
    float4 c0 = bf, c1 = bf, c2 = bf, c3 = bf;

    for (int k = 0; k < K; k += 4) {
        int src = k >> 2;
        #pragma unroll
        for (int kk = 0; kk < 4; kk++) {
            float4 wv = __ldg((const float4*)(W + (size_t)(k + kk) * DIM) + lane);
            float s0 = __shfl_sync(0xffffffffu, ((const float*)&a0)[kk], src);
            float s1 = __shfl_sync(0xffffffffu, ((const float*)&a1)[kk], src);
            float s2 = __shfl_sync(0xffffffffu, ((const float*)&a2)[kk], src);
            float s3 = __shfl_sync(0xffffffffu, ((const float*)&a3)[kk], src);
            fma4(c0, s0, wv); fma4(c1, s1, wv); fma4(c2, s2, wv); fma4(c3, s3, wv);
        }
    }
    gemm_store(C + (size_t)(r0 + 0) * DIM, lane, c0);
    gemm_store(C + (size_t)(r0 + 1) * DIM, lane, c1);
    gemm_store(C + (size_t)(r0 + 2) * DIM, lane, c2);
    gemm_store(C + (size_t)(r0 + 3) * DIM, lane, c3);
}

// ---------------------------------------------------------------------------
// 0) prep: zero counters + convert f1/f2/word_emb to fp16 + POS layer-1 GEMM
#define CNT4 (CTOT / 4)              // 15015
#define F1U  (N_WORD * DIM / 4)      // 640000
#define F2U  (N_ENT  * DIM / 4)      // 320000
#define WEU  (N_ENT  * D_WEMB / 4)   // 750000
#define PREP_UNITS (CNT4 + F1U + F2U + WEU)

__global__ void prep_kernel(const float* __restrict__ f1, const float* __restrict__ f2,
                            const float* __restrict__ wemb, const float* __restrict__ f3,
                            const float* __restrict__ W3, const float* __restrict__ b3)
{
    if (blockIdx.x == 0) {
        int lane = threadIdx.x & 31;
        for (int w = threadIdx.x >> 5; w < N_POS / 4; w += blockDim.x >> 5)
            gemm4_rows<false>(f3, W3, b3, g_g3, 4 * w, D_POS_IN, lane);
        return;
    }
    int stride = (gridDim.x - 1) * blockDim.x;
    for (int u = (blockIdx.x - 1) * blockDim.x + threadIdx.x; u < PREP_UNITS; u += stride) {
        if (u < CNT4) {
            ((int4*)g_cnt)[u] = make_int4(0, 0, 0, 0);
        } else if (u < CNT4 + F1U) {
            int i = u - CNT4;
            st_h4(g_f1h, i, __ldg((const float4*)f1 + i));
        } else if (u < CNT4 + F1U + F2U) {
            int i = u - (CNT4 + F1U);
            st_h4(g_f2h, i, __ldg((const float4*)f2 + i));
        } else {
            int i = u - (CNT4 + F1U + F2U);
            st_h4(g_wembh, i, __ldg((const float4*)wemb + i));
        }
    }
}

// ---------------------------------------------------------------------------
// 1) fused histogram over all 6 adjacencies
__global__ void hist_kernel(EdgePtrs ep) {
    int e = blockIdx.x * blockDim.x + threadIdx.x;
    if (e >= TOT_E) return;
    int gi;
    if      (e < B22) gi = C11 + __ldg(ep.r11 + (e - B11));
    else if (e < B33) gi = C22 + __ldg(ep.r22 + (e - B22));
    else if (e < B01) gi = C33 + __ldg(ep.r33 + (e - B33));
    else if (e < B02) gi = C01 + __ldg(ep.r01 + (e - B01));
    else if (e < B03) gi = C02 + __ldg(ep.r02 + (e - B02));
    else              gi = C03 + __ldg(ep.r03 + (e - B03));
    atomicAdd(g_cnt + gi, 1);
}

// 2) single-block exclusive scan of the counters -> g_off
__global__ void scan_kernel() {
    __shared__ int sp[1024];
    const int tid = threadIdx.x;
    const int per = (CTOT + 1023) / 1024;   // 59
    int lo = tid * per;
    int hi = lo + per; if (hi > CTOT) hi = CTOT;
    if (lo > CTOT) lo = CTOT;
    int s = 0;
    for (int i = lo; i < hi; i++) s += g_cnt[i];
    sp[tid] = s;
    __syncthreads();
    for (int d = 1; d < 1024; d <<= 1) {
        int v = (tid >= d) ? sp[tid - d] : 0;
        __syncthreads();
        sp[tid] += v;
        __syncthreads();
    }
    int run = (tid > 0) ? sp[tid - 1] : 0;
    for (int i = lo; i < hi; i++) {
        g_off[i] = run;
        run += g_cnt[i];
    }
}

// 3) bucket scatter; bumps g_off in place (afterwards g_off = inclusive prefix)
__global__ void bucket_kernel(EdgePtrs ep) {
    int e = blockIdx.x * blockDim.x + threadIdx.x;
    if (e >= TOT_E) return;
    int r, c, cb; float v;
    if (e < B22)      { int i = e - B11; r = __ldg(ep.r11+i); c = __ldg(ep.c11+i); v = __ldg(ep.v11+i); cb = C11; }
    else if (e < B33) { int i = e - B22; r = __ldg(ep.r22+i); c = __ldg(ep.c22+i); v = __ldg(ep.v22+i); cb = C22; }
    else if (e < B01) { int i = e - B33; r = __ldg(ep.r33+i); c = __ldg(ep.c33+i); v = __ldg(ep.v33+i); cb = C33; }
    else if (e < B02) { int i = e - B01; r = __ldg(ep.r01+i); c = __ldg(ep.c01+i); v = __ldg(ep.v01+i); cb = C01; }
    else if (e < B03) { int i = e - B02; r = __ldg(ep.r02+i); c = __ldg(ep.c02+i); v = __ldg(ep.v02+i); cb = C02; }
    else              { int i = e - B03; r = __ldg(ep.r03+i); c = __ldg(ep.c03+i); v = __ldg(ep.v03+i); cb = C03; }
    int pos = atomicAdd(g_off + cb + r, 1);
    g_sorted[pos] = make_float2(__int_as_float(c), v);
}

// ---------------------------------------------------------------------------
// 4/6) fused layer-1 / layer-2 SpMM over all three node types
template <int LAYER>
__global__ void spmm_l_kernel() {
    int w    = (blockIdx.x * blockDim.x + threadIdx.x) >> 5;
    int lane = threadIdx.x & 31;
    if (w >= N_WORD + N_ENT + N_POS) return;
    const __half* x; void* outp; int gi;
    if (w < N_WORD) {
        gi = C11 + w;
        x = (LAYER == 1) ? g_f1h : g_g1;
        outp = (LAYER == 1) ? (void*)(g_tmpA + (size_t)w * DIM)
                            : (void*)(g_tmpB + (size_t)w * DIM);
    } else if (w < N_WORD + N_ENT) {
        int r = w - N_WORD;
        gi = C22 + r;
        x = (LAYER == 1) ? g_f2h : g_g2;
        outp = (LAYER == 1) ? (void*)(g_tmp2 + (size_t)r * DIM)
                            : (void*)(g_tmp2b + (size_t)r * DIM);
    } else {
        int r = w - (N_WORD + N_ENT);
        gi = C33 + r;
        x = (LAYER == 1) ? g_g3 : g_g3b;
        outp = (LAYER == 1) ? (void*)(g_tmp3 + (size_t)r * DIM)
                            : (void*)(g_tmp3b + (size_t)r * DIM);
    }
    float4 sel = spmm_row_sel<false>(gi, x, lane);
    int unit = 2 * (lane & 15) + (lane >> 4);
    if (LAYER == 1) ((float4*)outp)[unit] = sel;
    else            st_h4((__half*)outp, unit, sel);
}

// 5) fused layer-2 projections for all three types (relu on input): K=128
__global__ void gemm_l2_kernel(const float* __restrict__ W1, const float* __restrict__ b1,
                               const float* __restrict__ W2, const float* __restrict__ b2,
                               const float* __restrict__ Wp, const float* __restrict__ bp) {
    int w    = (blockIdx.x * blockDim.x + threadIdx.x) >> 5;
    int lane = threadIdx.x & 31;
    const int WW = N_WORD / 4, WE = WW + N_ENT / 4, WP = WE + N_POS / 4;
    if (w >= WP) return;
    if (w < WW)       gemm4_rows<true>(g_tmpA, W1, b1, g_g1,  4 * w,        DIM, lane);
    else if (w < WE)  gemm4_rows<true>(g_tmp2, W2, b2, g_g2,  4 * (w - WW), DIM, lane);
    else              gemm4_rows<true>(g_tmp3, Wp, bp, g_g3b, 4 * (w - WE), DIM, lane);
}

// ---------------------------------------------------------------------------
// 7) fused doc aggregation + relu(source) + wemb concat + L2 norm
__global__ void docagg_kernel(float* __restrict__ out) {
    int w    = (blockIdx.x * blockDim.x + threadIdx.x) >> 5;
    int lane = threadIdx.x & 31;
    if (w >= 3 * N_DOC) return;
    float* out1 = out;
    float* out2 = out + (size_t)N_DOC * DIM;
    float* out3 = out2 + (size_t)N_DOC * (DIM + D_WEMB);

    if (w < N_DOC || w >= 2 * N_DOC) {
        bool first = (w < N_DOC);
        int row = first ? w : (w - 2 * N_DOC);
        int gi  = first ? (C01 + row) : (C03 + row);
        const __half* x = first ? g_tmpB : g_tmp3b;
        float4 sel = spmm_row_sel<true>(gi, x, lane);
        float ss = dot4(sel);
        #pragma unroll
        for (int o = 16; o; o >>= 1) ss += __shfl_xor_sync(0xffffffffu, ss, o);
        float inv = 1.f / (sqrtf(ss) + EPSN);
        float* dst = (first ? out1 : out3) + (size_t)row * DIM;
        int unit = 2 * (lane & 15) + (lane >> 4);
        ((float4*)dst)[unit] = make_float4(sel.x*inv, sel.y*inv, sel.z*inv, sel.w*inv);
    } else {
        // entities -> out2: 128 feature cols + 300 word_emb cols, norm over 428
        int row = w - N_DOC;
        int gi = C02 + row;
        int s = __ldg(g_off + gi - 1);
        int e = __ldg(g_off + gi);
        float4 aF = make_float4(0,0,0,0), w0 = aF, w1 = aF, w2 = aF;
        #pragma unroll 2
        for (int k = s; k < e; ++k) {
            float2 cv = __ldg(&g_sorted[k]);
            int c = __float_as_int(cv.x);
            float v = cv.y;
            float4 t = relu4(ldg_h4(g_tmp2b + (size_t)c * DIM, lane));
            fma4(aF, v, t);
            const __half* ws = g_wembh + (size_t)c * D_WEMB;  // 75 h4-units
            fma4(w0, v, ldg_h4(ws, lane));
            fma4(w1, v, ldg_h4(ws, lane + 32));
            if (lane < 11) fma4(w2, v, ldg_h4(ws, lane + 64));
        }
        float ss = dot4(aF) + dot4(w0) + dot4(w1);
        if (lane < 11) ss += dot4(w2);
        #pragma unroll
        for (int o = 16; o; o >>= 1) ss += __shfl_xor_sync(0xffffffffu, ss, o);
        float inv = 1.f / (sqrtf(ss) + EPSN);
        float* rowp = out2 + (size_t)row * (DIM + D_WEMB);
        ((float4*)rowp)[lane] = make_float4(aF.x*inv, aF.y*inv, aF.z*inv, aF.w*inv);
        float4* wr = (float4*)(rowp + DIM);
        wr[lane]      = make_float4(w0.x*inv, w0.y*inv, w0.z*inv, w0.w*inv);
        wr[lane + 32] = make_float4(w1.x*inv, w1.y*inv, w1.z*inv, w1.w*inv);
        if (lane < 11)
            wr[lane + 64] = make_float4(w2.x*inv, w2.y*inv, w2.z*inv, w2.w*inv);
    }
}

// ---------------------------------------------------------------------------
extern "C" void kernel_launch(void* const* d_in, const int* in_sizes, int n_in,
                              void* d_out, int out_size)
{
    const float* f1       = (const float*)d_in[0];
    const float* f2       = (const float*)d_in[1];
    const float* f3       = (const float*)d_in[2];
    const float* word_emb = (const float*)d_in[3];

    EdgePtrs ep;
    ep.r11 = (const int*)d_in[4];  ep.c11 = (const int*)d_in[5];  ep.v11 = (const float*)d_in[6];
    ep.r22 = (const int*)d_in[7];  ep.c22 = (const int*)d_in[8];  ep.v22 = (const float*)d_in[9];
    ep.r33 = (const int*)d_in[10]; ep.c33 = (const int*)d_in[11]; ep.v33 = (const float*)d_in[12];
    ep.r01 = (const int*)d_in[13]; ep.c01 = (const int*)d_in[14]; ep.v01 = (const float*)d_in[15];
    ep.r02 = (const int*)d_in[16]; ep.c02 = (const int*)d_in[17]; ep.v02 = (const float*)d_in[18];
    ep.r03 = (const int*)d_in[19]; ep.c03 = (const int*)d_in[20]; ep.v03 = (const float*)d_in[21];

    const float* W3   = (const float*)d_in[22];
    const float* b3   = (const float*)d_in[23];
    const float* W1_2 = (const float*)d_in[24];
    const float* b1_2 = (const float*)d_in[25];
    const float* W2_2 = (const float*)d_in[26];
    const float* b2_2 = (const float*)d_in[27];
    const float* W3_2 = (const float*)d_in[28];
    const float* b3_2 = (const float*)d_in[29];

    const int TB = 256;
    const int GRID_PREP = 2048 + 1;
    const int GRID_E    = (TOT_E + TB - 1) / TB;
    const int GRID_SPMM = ((N_WORD + N_ENT + N_POS) * 32 + TB - 1) / TB;
    const int GRID_GEMM = (((N_WORD + N_ENT + N_POS) / 4) * 32 + TB - 1) / TB;
    const int GRID_DOC  = (3 * N_DOC * 32 + TB - 1) / TB;

    prep_kernel<<<GRID_PREP, TB>>>(f1, f2, word_emb, f3, W3, b3);
    hist_kernel<<<GRID_E, TB>>>(ep);
    scan_kernel<<<1, 1024>>>();
    bucket_kernel<<<GRID_E, TB>>>(ep);

    spmm_l_kernel<1><<<GRID_SPMM, TB>>>();
    gemm_l2_kernel<<<GRID_GEMM, TB>>>(W1_2, b1_2, W2_2, b2_2, W3_2, b3_2);
    spmm_l_kernel<2><<<GRID_SPMM, TB>>>();

    docagg_kernel<<<GRID_DOC, TB>>>((float*)d_out);
}